// round 4
// baseline (speedup 1.0000x reference)
#include <cuda_runtime.h>

// Problem constants
#define NROWS 65536
#define KCODES 8192
#define DDIM 512

// Scratch (static __device__ globals; no runtime allocation allowed)
__device__ float g_zn[(size_t)NROWS * DDIM];                 // normalized z   (128 MB)
__device__ float g_cb[(size_t)KCODES * DDIM];                // normalized codebook (16 MB)
__device__ float g_ncb[KCODES];                              // ||cb_k||^2
__device__ unsigned long long g_best[NROWS];                 // packed (score_bits<<32)|idx

// ---------------- packed f32x2 helpers (FFMA2) ----------------
__device__ __forceinline__ unsigned long long pack_dup(float x) {
    unsigned long long r;
    asm("mov.b64 %0, {%1, %1};" : "=l"(r) : "f"(x));
    return r;
}
__device__ __forceinline__ void fma2(unsigned long long& d, unsigned long long a,
                                     unsigned long long b) {
    asm("fma.rn.f32x2 %0, %1, %2, %0;" : "+l"(d) : "l"(a), "l"(b));
}
__device__ __forceinline__ void unpack2(unsigned long long v, float& lo, float& hi) {
    asm("mov.b64 {%0, %1}, %2;" : "=f"(lo), "=f"(hi) : "l"(v));
}

// Monotonic float->uint mapping so (score,idx) packs into a u64 that orders
// lexicographically: smaller score first, then smaller index (matches
// jnp.argmin first-occurrence tie-break).
__device__ __forceinline__ unsigned long long score_key(float s, int n) {
    unsigned u = __float_as_uint(s);
    u = (u & 0x80000000u) ? ~u : (u | 0x80000000u);
    return ((unsigned long long)u << 32) | (unsigned)n;
}

// ---------------- row normalization ----------------
// One block per row, 128 threads, D=512 -> 4 floats/thread (float4).
__global__ void normalize_z_kernel(const float* __restrict__ z) {
    const int row = blockIdx.x;
    const int tid = threadIdx.x;
    __shared__ float sbuf[4];

    float4 v = *(const float4*)(z + (size_t)row * DDIM + tid * 4);
    float s = v.x * v.x + v.y * v.y + v.z * v.z + v.w * v.w;
    #pragma unroll
    for (int off = 16; off; off >>= 1) s += __shfl_down_sync(0xffffffffu, s, off);
    if ((tid & 31) == 0) sbuf[tid >> 5] = s;
    __syncthreads();
    float total = sbuf[0] + sbuf[1] + sbuf[2] + sbuf[3];
    float inv = 1.0f / fmaxf(sqrtf(total), 1e-12f);
    float4 o;
    o.x = v.x * inv; o.y = v.y * inv; o.z = v.z * inv; o.w = v.w * inv;
    *(float4*)(g_zn + (size_t)row * DDIM + tid * 4) = o;
}

__global__ void normalize_cb_kernel(const float* __restrict__ e) {
    const int row = blockIdx.x;
    const int tid = threadIdx.x;
    __shared__ float sbuf[4];

    float4 v = *(const float4*)(e + (size_t)row * DDIM + tid * 4);
    float s = v.x * v.x + v.y * v.y + v.z * v.z + v.w * v.w;
    #pragma unroll
    for (int off = 16; off; off >>= 1) s += __shfl_down_sync(0xffffffffu, s, off);
    if ((tid & 31) == 0) sbuf[tid >> 5] = s;
    __syncthreads();
    float total = sbuf[0] + sbuf[1] + sbuf[2] + sbuf[3];
    float inv = 1.0f / fmaxf(sqrtf(total), 1e-12f);
    float4 o;
    o.x = v.x * inv; o.y = v.y * inv; o.z = v.z * inv; o.w = v.w * inv;
    *(float4*)(g_cb + (size_t)row * DDIM + tid * 4) = o;

    // ||cb||^2 of the *rounded* normalized row (mirrors reference: sum(cb*cb))
    float s2 = o.x * o.x + o.y * o.y + o.z * o.z + o.w * o.w;
    #pragma unroll
    for (int off = 16; off; off >>= 1) s2 += __shfl_down_sync(0xffffffffu, s2, off);
    __syncthreads();
    if ((tid & 31) == 0) sbuf[tid >> 5] = s2;
    __syncthreads();
    if (tid == 0) g_ncb[row] = sbuf[0] + sbuf[1] + sbuf[2] + sbuf[3];
}

__global__ void init_best_kernel() {
    int i = blockIdx.x * blockDim.x + threadIdx.x;
    if (i < NROWS) g_best[i] = 0xFFFFFFFFFFFFFFFFull;
}

// ---------------- fused GEMM + per-row argmin ----------------
// Tile: 128 rows (z) x 128 codes, 256 threads, 8x8 per thread.
// Accumulators packed f32x2 along n (FFMA2 doubles fp32 FMA throughput).
// Epilogue: score = ||cb_n||^2 - 2*dot, per-row min folded across the block,
// merged globally with a 64-bit atomicMin on packed (score,idx).
__global__ __launch_bounds__(256, 2) void vq_gemm_kernel() {
    __shared__ __align__(16) float As[8][128];   // [k][m]
    __shared__ __align__(16) float Bs[8][128];   // [k][n]
    __shared__ float ncbs[128];

    const int tid = threadIdx.x;
    const int tx = tid & 15;        // n direction
    const int ty = tid >> 4;        // m direction
    const int m0 = blockIdx.y * 128;
    const int n0 = blockIdx.x * 128;

    const int lrow = tid >> 1;          // 0..127
    const int lk4  = (tid & 1) * 4;     // 0 or 4

    if (tid < 128) ncbs[tid] = g_ncb[n0 + tid];

    unsigned long long acc[8][4];
    #pragma unroll
    for (int i = 0; i < 8; i++)
        #pragma unroll
        for (int j = 0; j < 4; j++) acc[i][j] = 0ull;

    const float* aptr = g_zn + (size_t)(m0 + lrow) * DDIM + lk4;
    const float* bptr = g_cb + (size_t)(n0 + lrow) * DDIM + lk4;

    float4 av = *(const float4*)aptr;
    float4 bv = *(const float4*)bptr;

    for (int kc = 0; kc < DDIM; kc += 8) {
        __syncthreads();
        As[lk4 + 0][lrow] = av.x; As[lk4 + 1][lrow] = av.y;
        As[lk4 + 2][lrow] = av.z; As[lk4 + 3][lrow] = av.w;
        Bs[lk4 + 0][lrow] = bv.x; Bs[lk4 + 1][lrow] = bv.y;
        Bs[lk4 + 2][lrow] = bv.z; Bs[lk4 + 3][lrow] = bv.w;
        __syncthreads();
        if (kc + 8 < DDIM) {   // prefetch next chunk; latency hidden by compute
            av = *(const float4*)(aptr + kc + 8);
            bv = *(const float4*)(bptr + kc + 8);
        }
        #pragma unroll
        for (int kk = 0; kk < 8; kk++) {
            float4 a0 = *(const float4*)&As[kk][ty * 8];
            float4 a1 = *(const float4*)&As[kk][ty * 8 + 4];
            unsigned long long b[4];
            const unsigned long long* bp =
                (const unsigned long long*)&Bs[kk][tx * 8];
            b[0] = bp[0]; b[1] = bp[1]; b[2] = bp[2]; b[3] = bp[3];
            float a[8] = {a0.x, a0.y, a0.z, a0.w, a1.x, a1.y, a1.z, a1.w};
            #pragma unroll
            for (int i = 0; i < 8; i++) {
                unsigned long long a2 = pack_dup(a[i]);
                #pragma unroll
                for (int j = 0; j < 4; j++) fma2(acc[i][j], a2, b[j]);
            }
        }
    }

    // Epilogue: per-row (score,idx) min, reduce across the 16 lanes that share
    // a row (contiguous half-warp -> shfl width 16), then global atomicMin.
    #pragma unroll
    for (int i = 0; i < 8; i++) {
        const int m = m0 + ty * 8 + i;
        unsigned long long best = 0xFFFFFFFFFFFFFFFFull;
        #pragma unroll
        for (int j = 0; j < 4; j++) {
            float d0, d1;
            unpack2(acc[i][j], d0, d1);
            const int nl = tx * 8 + 2 * j;
            float s0 = ncbs[nl]     - 2.0f * d0;
            float s1 = ncbs[nl + 1] - 2.0f * d1;
            unsigned long long k0 = score_key(s0, n0 + nl);
            unsigned long long k1 = score_key(s1, n0 + nl + 1);
            if (k0 < best) best = k0;
            if (k1 < best) best = k1;
        }
        #pragma unroll
        for (int off = 8; off; off >>= 1) {
            unsigned long long o = __shfl_down_sync(0xffffffffu, best, off, 16);
            if (o < best) best = o;
        }
        if (tx == 0) atomicMin(&g_best[m], best);
    }
}

// ---------------- gather + projection + index output ----------------
__global__ void proj_kernel(float* __restrict__ out, int out_size) {
    const int row = blockIdx.x;
    const int tid = threadIdx.x;   // 128
    __shared__ float sbuf[4];

    const int idx = (int)(g_best[row] & 0xFFFFFFFFull);
    const float4 zv = *(const float4*)(g_zn + (size_t)row * DDIM + tid * 4);
    const float4 cv = *(const float4*)(g_cb + (size_t)idx * DDIM + tid * 4);
    float p = zv.x * cv.x + zv.y * cv.y + zv.z * cv.z + zv.w * cv.w;
    #pragma unroll
    for (int off = 16; off; off >>= 1) p += __shfl_down_sync(0xffffffffu, p, off);
    if ((tid & 31) == 0) sbuf[tid >> 5] = p;
    __syncthreads();
    const float dot = sbuf[0] + sbuf[1] + sbuf[2] + sbuf[3];

    float4 o;
    o.x = dot * cv.x; o.y = dot * cv.y; o.z = dot * cv.z; o.w = dot * cv.w;
    *(float4*)(out + (size_t)row * DDIM + tid * 4) = o;

    if (tid == 0 && out_size >= NROWS * DDIM + NROWS)
        out[(size_t)NROWS * DDIM + row] = (float)idx;
}

extern "C" void kernel_launch(void* const* d_in, const int* in_sizes, int n_in,
                              void* d_out, int out_size) {
    const float* z   = (const float*)d_in[0];
    const float* emb = (const float*)d_in[1];
    // Defensive: identify tensors by size in case of ordering surprises.
    if (n_in >= 2 && in_sizes[0] == KCODES * DDIM && in_sizes[1] == NROWS * DDIM) {
        const float* t = z; z = emb; emb = t;
    }

    normalize_z_kernel<<<NROWS, 128>>>(z);
    normalize_cb_kernel<<<KCODES, 128>>>(emb);
    init_best_kernel<<<NROWS / 256, 256>>>();

    dim3 grid(KCODES / 128, NROWS / 128);   // (n-tiles, m-tiles)
    vq_gemm_kernel<<<grid, 256>>>();

    proj_kernel<<<NROWS, 128>>>((float*)d_out, out_size);
}